// round 2
// baseline (speedup 1.0000x reference)
#include <cuda_runtime.h>

#define NB   16
#define FW   512
#define SW   128
#define IMG  (SW*SW)        // 16384
#define NPIX (NB*IMG)       // 262144
#define SP   129            // padded smem row stride (conflict-free both axes)

// ---------------- device scratch (no cudaMalloc allowed) ----------------
__device__ float g_praw [2*NPIX];   // [prev(16 imgs) | curr(16 imgs)] pre-blur
__device__ float g_pblur[2*NPIX];   // blurred
__device__ float g_rain [NPIX];
__device__ unsigned long long g_best[NPIX];
__device__ float g_flow0[2*NPIX];   // [fx | fy] pre-blur
__device__ float g_flowb[2*NPIX];   // [fx | fy] blurred*rain
__device__ float g_partial[1024];

// Gaussian k1 (sigma=1, r=3), normalized
__constant__ float GW[7] = {0.0044330482f, 0.0540055826f, 0.2420362293f,
                            0.3990502800f,
                            0.2420362293f, 0.0540055826f, 0.0044330482f};

// ---------------- K1: log1p + exact 4x downsample + rain -----------------
__global__ void k_prepare(const float* __restrict__ target, const float* __restrict__ ref) {
    int i = blockIdx.x * 256 + threadIdx.x;
    if (i >= NPIX) return;
    int b = i >> 14;
    int p = i & (IMG - 1);
    int y = p >> 7, x = p & 127;
    const float* tb = target + b * (FW * FW);
    const float* rb = ref    + b * (FW * FW);
    int o00 = (4 * y + 1) * FW + (4 * x + 1);
    float t00 = tb[o00], t01 = tb[o00 + 1], t10 = tb[o00 + FW], t11 = tb[o00 + FW + 1];
    float r00 = rb[o00], r01 = rb[o00 + 1], r10 = rb[o00 + FW], r11 = rb[o00 + FW + 1];
    float tm = 0.25f * (t00 + t01 + t10 + t11);
    g_rain[i] = (tm >= 0.1f) ? 1.0f : 0.0f;
    float cw = 0.25f * (log1pf(fmaxf(t00, 0.f)) + log1pf(fmaxf(t01, 0.f)) +
                        log1pf(fmaxf(t10, 0.f)) + log1pf(fmaxf(t11, 0.f)));
    float pw = 0.25f * (log1pf(fmaxf(r00, 0.f)) + log1pf(fmaxf(r01, 0.f)) +
                        log1pf(fmaxf(r10, 0.f)) + log1pf(fmaxf(r11, 0.f)));
    g_praw[i]        = pw;   // prev (ref)
    g_praw[NPIX + i] = cw;   // curr (target)
    g_best[i] = ~0ull;
}

// ---------------- separable 7x7 blur, edge-replicate, per-image block ----
// mode 0: g_praw -> g_pblur (no rain); mode 1: g_flow0 -> g_flowb (*rain)
__global__ void k_blur(int mode) {
    extern __shared__ float s[];
    float* s_in = s;
    float* s_h  = s + IMG;
    int img = blockIdx.x;            // 0..31
    const float* in  = (mode == 0 ? g_praw  : g_flow0) + img * IMG;
    float*       out = (mode == 0 ? g_pblur : g_flowb) + img * IMG;
    for (int i = threadIdx.x; i < IMG; i += blockDim.x) s_in[i] = in[i];
    __syncthreads();
    for (int i = threadIdx.x; i < IMG; i += blockDim.x) {
        int y = i >> 7, x = i & 127;
        float a = 0.f;
        #pragma unroll
        for (int u = -3; u <= 3; u++) {
            int xc = min(max(x + u, 0), 127);
            a += GW[u + 3] * s_in[(y << 7) + xc];
        }
        s_h[i] = a;
    }
    __syncthreads();
    const float* rimg = g_rain + (img & 15) * IMG;
    for (int i = threadIdx.x; i < IMG; i += blockDim.x) {
        int y = i >> 7, x = i & 127;
        float a = 0.f;
        #pragma unroll
        for (int u = -3; u <= 3; u++) {
            int yc = min(max(y + u, 0), 127);
            a += GW[u + 3] * s_h[(yc << 7) + x];
        }
        if (mode) a *= rimg[i];
        out[i] = a;
    }
}

// ---------------- K2: 169-shift patch cost + argmin ----------------------
// block = (batch, dyi) : 16*13 = 208 blocks, 256 threads
// smem: prev[128][129] curr[128][129] hsum[128][129] + u8 bestidx[128*128]
__global__ void __launch_bounds__(256) k_cost() {
    extern __shared__ float sm[];
    float* s_prev = sm;
    float* s_curr = sm + SW * SP;
    float* s_hsum = sm + 2 * SW * SP;
    unsigned char* s_bi = (unsigned char*)(sm + 3 * SW * SP);

    int b   = blockIdx.x / 13;
    int dyi = blockIdx.x - b * 13;
    int dy  = dyi - 6;
    int t   = threadIdx.x;

    const float* pb = g_pblur + b * IMG;
    const float* cb = g_pblur + NPIX + b * IMG;

    for (int i = t; i < IMG; i += 256) {
        int r = i >> 7, c = i & 127;
        s_prev[r * SP + c] = pb[i];
        int rs = min(max(r + dy, 0), 127);
        s_curr[r * SP + c] = cb[(rs << 7) + c];   // pre-apply dy (clamped rows)
    }
    __syncthreads();

    const int col  = t & 127;          // vsum ownership
    const int rseg = (t >> 7) << 6;    // rows [rseg, rseg+64)
    const int hr   = t & 127;          // hsum row
    const int hc0  = (t >> 7) << 6;    // hsum col segment

    float bestc[64];
    #pragma unroll
    for (int k = 0; k < 64; k++) bestc[k] = 3.0e38f;

    #pragma unroll 1
    for (int dxi = 0; dxi < 13; dxi++) {
        int dx = dxi - 6;
        // ---- horizontal 21-window sliding sum of d^2 (zero-padded) ----
        {
            const float* pr = s_prev + hr * SP;
            const float* cr = s_curr + hr * SP;
            float w = 0.f;
            #pragma unroll
            for (int u = -10; u <= 10; u++) {
                int c = hc0 + u;
                if ((unsigned)c < 128u) {
                    int cc = min(max(c + dx, 0), 127);
                    float d = pr[c] - cr[cc];
                    w += d * d;
                }
            }
            float* hrow = s_hsum + hr * SP;
            #pragma unroll 4
            for (int c = hc0; c < hc0 + 64; c++) {
                hrow[c] = w;
                int ca = c + 11;
                if (ca < 128) {
                    int cc = min(ca + dx, 127);          // ca>=11 => ca+dx>=5
                    float d = pr[ca] - cr[cc];
                    w += d * d;
                }
                int cs = c - 10;
                if (cs >= 0) {
                    int cc = min(max(cs + dx, 0), 127);
                    float d = pr[cs] - cr[cc];
                    w -= d * d;
                }
            }
        }
        __syncthreads();
        // ---- vertical 21-window sliding sum + running argmin ----
        {
            float w = 0.f;
            #pragma unroll
            for (int u = -10; u <= 10; u++) {
                int r = rseg + u;
                if ((unsigned)r < 128u) w += s_hsum[r * SP + col];
            }
            unsigned char idx = (unsigned char)(dyi * 13 + dxi);
            #pragma unroll
            for (int k = 0; k < 64; k++) {
                if (w < bestc[k]) { bestc[k] = w; s_bi[((rseg + k) << 7) + col] = idx; }
                int ra = rseg + k + 11;
                if (ra < 128) w += s_hsum[ra * SP + col];
                int rb2 = rseg + k - 10;
                if (rb2 >= 0) w -= s_hsum[rb2 * SP + col];
            }
        }
        __syncthreads();
    }
    // merge across dy-blocks: packed (costbits<<32 | idx) min == argmin w/ first-index ties
    unsigned long long* gb = g_best + b * IMG;
    #pragma unroll 4
    for (int k = 0; k < 64; k++) {
        int r = rseg + k;
        unsigned long long key =
            ((unsigned long long)__float_as_uint(bestc[k]) << 32) |
            (unsigned long long)s_bi[(r << 7) + col];
        atomicMin(gb + (r << 7) + col, key);
    }
}

// ---------------- K3: best -> (fx,fy) * rain ------------------------------
__global__ void k_flow() {
    int i = blockIdx.x * 256 + threadIdx.x;
    if (i >= NPIX) return;
    unsigned idx = (unsigned)(g_best[i] & 0xffffffffull);
    float rain = g_rain[i];
    int dyi = idx / 13;
    int dxi = idx - dyi * 13;
    g_flow0[i]        = (float)(dxi - 6) * rain;
    g_flow0[NPIX + i] = (float)(dyi - 6) * rain;
}

// ---------------- K4: upsample flow + warp ref + Huber + mask + reduce ----
__global__ void k_loss(const float* __restrict__ pred, const float* __restrict__ target,
                       const float* __restrict__ ref) {
    const int total = NB * FW * FW;
    float acc = 0.f;
    for (int idx = blockIdx.x * blockDim.x + threadIdx.x; idx < total;
         idx += gridDim.x * blockDim.x) {
        int b  = idx >> 18;
        int p  = idx & 262143;
        int oy = p >> 9, ox = p & 511;
        // bilinear upsample coords (half-pixel, clamped like _resize)
        float sx = 0.25f * ((float)ox + 0.5f) - 0.5f; sx = fmaxf(sx, 0.f);
        int ix0 = (int)sx; float wx = sx - (float)ix0; int ix1 = min(ix0 + 1, 127);
        float sy = 0.25f * ((float)oy + 0.5f) - 0.5f; sy = fmaxf(sy, 0.f);
        int iy0 = (int)sy; float wy = sy - (float)iy0; int iy1 = min(iy0 + 1, 127);
        const float* fxp = g_flowb + b * IMG;
        const float* fyp = g_flowb + NPIX + b * IMG;
        int o00 = (iy0 << 7) + ix0, o01 = (iy0 << 7) + ix1;
        int o10 = (iy1 << 7) + ix0, o11 = (iy1 << 7) + ix1;
        float w00 = (1.f - wy) * (1.f - wx), w01 = (1.f - wy) * wx;
        float w10 = wy * (1.f - wx),        w11 = wy * wx;
        float fx = (fxp[o00]*w00 + fxp[o01]*w01 + fxp[o10]*w10 + fxp[o11]*w11) * 4.0f;
        float fy = (fyp[o00]*w00 + fyp[o01]*w01 + fyp[o10]*w10 + fyp[o11]*w11) * 4.0f;
        // grid algebra collapses to: sample ref at (ox - fx, oy - fy), border clamp
        float X = fminf(fmaxf((float)ox - fx, 0.f), 511.f);
        float Y = fminf(fmaxf((float)oy - fy, 0.f), 511.f);
        int x0 = (int)X; float ax = X - (float)x0; int x1 = min(x0 + 1, 511);
        int y0 = (int)Y; float ay = Y - (float)y0; int y1 = min(y0 + 1, 511);
        const float* rb = ref + b * (FW * FW);
        float v00 = rb[y0 * FW + x0], v01 = rb[y0 * FW + x1];
        float v10 = rb[y1 * FW + x0], v11 = rb[y1 * FW + x1];
        float tv = v00 * (1.f - ay) * (1.f - ax) + v01 * (1.f - ay) * ax +
                   v10 * ay * (1.f - ax)         + v11 * ay * ax;
        float teacher = fmaxf(tv, 0.f);
        float d  = pred[idx] - teacher;
        float ad = fabsf(d);
        float l  = (ad < 0.2f) ? (0.5f * d * d) : (0.2f * (ad - 0.1f));
        float m  = (teacher > 0.05f || target[idx] > 0.05f) ? 1.f : 0.f;
        acc += l * m;
    }
    __shared__ float sred[256];
    sred[threadIdx.x] = acc;
    __syncthreads();
    for (int s = 128; s > 0; s >>= 1) {
        if (threadIdx.x < s) sred[threadIdx.x] += sred[threadIdx.x + s];
        __syncthreads();
    }
    if (threadIdx.x == 0) g_partial[blockIdx.x] = sred[0];
}

__global__ void k_final(float* __restrict__ out) {
    __shared__ float sred[1024];
    sred[threadIdx.x] = g_partial[threadIdx.x];
    __syncthreads();
    for (int s = 512; s > 0; s >>= 1) {
        if (threadIdx.x < s) sred[threadIdx.x] += sred[threadIdx.x + s];
        __syncthreads();
    }
    if (threadIdx.x == 0) out[0] = sred[0] * (1.0f / 4194304.0f);
}

// ---------------------------------------------------------------------------
extern "C" void kernel_launch(void* const* d_in, const int* in_sizes, int n_in,
                              void* d_out, int out_size) {
    const float* pred   = (const float*)d_in[0];
    const float* target = (const float*)d_in[1];
    const float* ref    = (const float*)d_in[2];
    float* out = (float*)d_out;

    const int blurSmem = 2 * IMG * (int)sizeof(float);            // 131072
    const int costSmem = 3 * SW * SP * (int)sizeof(float) + IMG;  // 214528
    cudaFuncSetAttribute(k_blur, cudaFuncAttributeMaxDynamicSharedMemorySize, blurSmem);
    cudaFuncSetAttribute(k_cost, cudaFuncAttributeMaxDynamicSharedMemorySize, costSmem);

    k_prepare<<<NPIX / 256, 256>>>(target, ref);
    k_blur<<<32, 256, blurSmem>>>(0);
    k_cost<<<NB * 13, 256, costSmem>>>();
    k_flow<<<NPIX / 256, 256>>>();
    k_blur<<<32, 256, blurSmem>>>(1);
    k_loss<<<1024, 256>>>(pred, target, ref);
    k_final<<<1, 1024>>>(out);
}

// round 3
// speedup vs baseline: 1.2816x; 1.2816x over previous
#include <cuda_runtime.h>

#define NB   16
#define FW   512
#define SW   128
#define IMG  (SW*SW)        // 16384
#define NPIX (NB*IMG)       // 262144
#define SP   129            // padded smem row stride (conflict-free both axes)

// ---------------- device scratch (no cudaMalloc allowed) ----------------
__device__ float g_praw [2*NPIX];   // [prev(16 imgs) | curr(16 imgs)] pre-blur
__device__ float g_pblur[2*NPIX];   // blurred
__device__ float g_rain [NPIX];
__device__ unsigned long long g_best[NPIX];
__device__ float g_flowb[2*NPIX];   // [fx | fy] blurred*rain
__device__ float g_partial[4096];

// Gaussian k1 (sigma=1, r=3), normalized
__constant__ float GW[7] = {0.0044330482f, 0.0540055826f, 0.2420362293f,
                            0.3990502800f,
                            0.2420362293f, 0.0540055826f, 0.0044330482f};

// ---------------- K1: log1p + exact 4x downsample + rain -----------------
__global__ void k_prepare(const float* __restrict__ target, const float* __restrict__ ref) {
    int i = blockIdx.x * 256 + threadIdx.x;
    if (i >= NPIX) return;
    int b = i >> 14;
    int p = i & (IMG - 1);
    int y = p >> 7, x = p & 127;
    const float* tb = target + b * (FW * FW);
    const float* rb = ref    + b * (FW * FW);
    int o00 = (4 * y + 1) * FW + (4 * x + 1);
    float t00 = tb[o00], t01 = tb[o00 + 1], t10 = tb[o00 + FW], t11 = tb[o00 + FW + 1];
    float r00 = rb[o00], r01 = rb[o00 + 1], r10 = rb[o00 + FW], r11 = rb[o00 + FW + 1];
    float tm = 0.25f * (t00 + t01 + t10 + t11);
    g_rain[i] = (tm >= 0.1f) ? 1.0f : 0.0f;
    float cw = 0.25f * (log1pf(fmaxf(t00, 0.f)) + log1pf(fmaxf(t01, 0.f)) +
                        log1pf(fmaxf(t10, 0.f)) + log1pf(fmaxf(t11, 0.f)));
    float pw = 0.25f * (log1pf(fmaxf(r00, 0.f)) + log1pf(fmaxf(r01, 0.f)) +
                        log1pf(fmaxf(r10, 0.f)) + log1pf(fmaxf(r11, 0.f)));
    g_praw[i]        = pw;   // prev (ref)
    g_praw[NPIX + i] = cw;   // curr (target)
    g_best[i] = ~0ull;
}

// ---------------- separable 7x7 blur, edge-replicate, per-image block ----
// mode 0: g_praw[imgBase+blk] -> g_pblur  (weights)
// mode 1: flow-from-(g_best,g_rain) -> g_flowb, output *= rain
__global__ void k_blur(int mode, int imgBase) {
    extern __shared__ float s[];
    float* s_in = s;
    float* s_h  = s + IMG;
    int img = imgBase + blockIdx.x;
    float* out = (mode == 0 ? g_pblur : g_flowb) + img * IMG;
    if (mode == 0) {
        const float* in = g_praw + img * IMG;
        for (int i = threadIdx.x; i < IMG; i += blockDim.x) s_in[i] = in[i];
    } else {
        // img 0..15 -> fx, 16..31 -> fy
        int gi0 = (img & 15) * IMG;
        bool isY = (img >= 16);
        for (int i = threadIdx.x; i < IMG; i += blockDim.x) {
            unsigned idx = (unsigned)(g_best[gi0 + i] & 0xffu);
            float rain = g_rain[gi0 + i];
            int dyi = (int)(idx / 13u);
            int dxi = (int)idx - dyi * 13;
            s_in[i] = (isY ? (float)(dyi - 6) : (float)(dxi - 6)) * rain;
        }
    }
    __syncthreads();
    for (int i = threadIdx.x; i < IMG; i += blockDim.x) {
        int y = i >> 7, x = i & 127;
        float a = 0.f;
        #pragma unroll
        for (int u = -3; u <= 3; u++) {
            int xc = min(max(x + u, 0), 127);
            a += GW[u + 3] * s_in[(y << 7) + xc];
        }
        s_h[i] = a;
    }
    __syncthreads();
    const float* rimg = g_rain + (img & 15) * IMG;
    for (int i = threadIdx.x; i < IMG; i += blockDim.x) {
        int y = i >> 7, x = i & 127;
        float a = 0.f;
        #pragma unroll
        for (int u = -3; u <= 3; u++) {
            int yc = min(max(y + u, 0), 127);
            a += GW[u + 3] * s_h[(yc << 7) + x];
        }
        if (mode) a *= rimg[i];
        out[i] = a;
    }
}

// ---------------- K2: 169-shift patch cost + argmin ----------------------
// block = (batch, dyi) : 16*13 = 208 blocks, 512 threads (16 warps for latency hiding)
// smem: prev[128][129] curr[128][129] hsum[128][129] + u8 bestidx[128*128]
__global__ void __launch_bounds__(512) k_cost() {
    extern __shared__ float sm[];
    float* s_prev = sm;
    float* s_curr = sm + SW * SP;
    float* s_hsum = sm + 2 * SW * SP;
    unsigned char* s_bi = (unsigned char*)(sm + 3 * SW * SP);

    int b   = blockIdx.x / 13;
    int dyi = blockIdx.x - b * 13;
    int dy  = dyi - 6;
    int t   = threadIdx.x;

    const float* pb = g_pblur + b * IMG;
    const float* cb = g_pblur + NPIX + b * IMG;

    for (int i = t; i < IMG; i += 512) {
        int r = i >> 7, c = i & 127;
        s_prev[r * SP + c] = pb[i];
        int rs = min(max(r + dy, 0), 127);
        s_curr[r * SP + c] = cb[(rs << 7) + c];   // pre-apply dy (clamped rows)
    }
    __syncthreads();

    const int col  = t & 127;          // vsum ownership
    const int rseg = (t >> 7) << 5;    // rows [rseg, rseg+32)
    const int hr   = t & 127;          // hsum row
    const int hc0  = (t >> 7) << 5;    // hsum col segment [hc0, hc0+32)

    float bestc[32];
    #pragma unroll
    for (int k = 0; k < 32; k++) bestc[k] = 3.0e38f;

    #pragma unroll 1
    for (int dxi = 0; dxi < 13; dxi++) {
        int dx = dxi - 6;
        // ---- horizontal 21-window sliding sum of d^2 (zero-padded) ----
        {
            const float* pr = s_prev + hr * SP;
            const float* cr = s_curr + hr * SP;
            float w = 0.f;
            #pragma unroll
            for (int u = -10; u <= 10; u++) {
                int c = hc0 + u;
                if ((unsigned)c < 128u) {
                    int cc = min(max(c + dx, 0), 127);
                    float d = pr[c] - cr[cc];
                    w += d * d;
                }
            }
            float* hrow = s_hsum + hr * SP;
            #pragma unroll 4
            for (int c = hc0; c < hc0 + 32; c++) {
                hrow[c] = w;
                int ca = c + 11;
                if (ca < 128) {
                    int cc = min(ca + dx, 127);          // ca>=11 => ca+dx>=5
                    float d = pr[ca] - cr[cc];
                    w += d * d;
                }
                int cs = c - 10;
                if (cs >= 0) {
                    int cc = min(max(cs + dx, 0), 127);
                    float d = pr[cs] - cr[cc];
                    w -= d * d;
                }
            }
        }
        __syncthreads();
        // ---- vertical 21-window sliding sum + running argmin ----
        {
            float w = 0.f;
            #pragma unroll
            for (int u = -10; u <= 10; u++) {
                int r = rseg + u;
                if ((unsigned)r < 128u) w += s_hsum[r * SP + col];
            }
            unsigned char idx = (unsigned char)(dyi * 13 + dxi);
            #pragma unroll
            for (int k = 0; k < 32; k++) {
                if (w < bestc[k]) { bestc[k] = w; s_bi[((rseg + k) << 7) + col] = idx; }
                int ra = rseg + k + 11;
                if (ra < 128) w += s_hsum[ra * SP + col];
                int rb2 = rseg + k - 10;
                if (rb2 >= 0) w -= s_hsum[rb2 * SP + col];
            }
        }
        __syncthreads();
    }
    // merge across dy-blocks: packed (costbits<<32 | idx) min == argmin w/ first-index ties
    unsigned long long* gb = g_best + b * IMG;
    #pragma unroll 4
    for (int k = 0; k < 32; k++) {
        int r = rseg + k;
        unsigned long long key =
            ((unsigned long long)__float_as_uint(bestc[k]) << 32) |
            (unsigned long long)s_bi[(r << 7) + col];
        atomicMin(gb + (r << 7) + col, key);
    }
}

// ---------------- K4: upsample flow + warp ref + Huber + mask + reduce ----
// 4 pixels (one float4 of pred/target) per thread
__global__ void k_loss(const float* __restrict__ pred, const float* __restrict__ target,
                       const float* __restrict__ ref) {
    int idx4 = blockIdx.x * blockDim.x + threadIdx.x;   // 0 .. 1048575
    int pix0 = idx4 << 2;
    int b  = pix0 >> 18;
    int p  = pix0 & 262143;
    int oy = p >> 9, ox0 = p & 511;

    float4 pv = *reinterpret_cast<const float4*>(pred   + pix0);
    float4 tv4 = *reinterpret_cast<const float4*>(target + pix0);
    const float pr4[4] = {pv.x, pv.y, pv.z, pv.w};
    const float tg4[4] = {tv4.x, tv4.y, tv4.z, tv4.w};

    // y-interp factors shared by the 4 pixels
    float sy = 0.25f * ((float)oy + 0.5f) - 0.5f; sy = fmaxf(sy, 0.f);
    int iy0 = (int)sy; float wy = sy - (float)iy0; int iy1 = min(iy0 + 1, 127);
    const float* fxp = g_flowb + b * IMG;
    const float* fyp = g_flowb + NPIX + b * IMG;
    const float* rb  = ref + b * (FW * FW);

    float acc = 0.f;
    #pragma unroll
    for (int j = 0; j < 4; j++) {
        int ox = ox0 + j;
        float sx = 0.25f * ((float)ox + 0.5f) - 0.5f; sx = fmaxf(sx, 0.f);
        int ix0 = (int)sx; float wx = sx - (float)ix0; int ix1 = min(ix0 + 1, 127);
        int o00 = (iy0 << 7) + ix0, o01 = (iy0 << 7) + ix1;
        int o10 = (iy1 << 7) + ix0, o11 = (iy1 << 7) + ix1;
        float w00 = (1.f - wy) * (1.f - wx), w01 = (1.f - wy) * wx;
        float w10 = wy * (1.f - wx),        w11 = wy * wx;
        float fx = (fxp[o00]*w00 + fxp[o01]*w01 + fxp[o10]*w10 + fxp[o11]*w11) * 4.0f;
        float fy = (fyp[o00]*w00 + fyp[o01]*w01 + fyp[o10]*w10 + fyp[o11]*w11) * 4.0f;
        // grid algebra collapses to: sample ref at (ox - fx, oy - fy), border clamp
        float X = fminf(fmaxf((float)ox - fx, 0.f), 511.f);
        float Y = fminf(fmaxf((float)oy - fy, 0.f), 511.f);
        int x0 = (int)X; float ax = X - (float)x0; int x1 = min(x0 + 1, 511);
        int y0 = (int)Y; float ay = Y - (float)y0; int y1 = min(y0 + 1, 511);
        float v00 = rb[y0 * FW + x0], v01 = rb[y0 * FW + x1];
        float v10 = rb[y1 * FW + x0], v11 = rb[y1 * FW + x1];
        float tv = v00 * (1.f - ay) * (1.f - ax) + v01 * (1.f - ay) * ax +
                   v10 * ay * (1.f - ax)         + v11 * ay * ax;
        float teacher = fmaxf(tv, 0.f);
        float d  = pr4[j] - teacher;
        float ad = fabsf(d);
        float l  = (ad < 0.2f) ? (0.5f * d * d) : (0.2f * (ad - 0.1f));
        float m  = (teacher > 0.05f || tg4[j] > 0.05f) ? 1.f : 0.f;
        acc += l * m;
    }
    __shared__ float sred[256];
    sred[threadIdx.x] = acc;
    __syncthreads();
    for (int s = 128; s > 0; s >>= 1) {
        if (threadIdx.x < s) sred[threadIdx.x] += sred[threadIdx.x + s];
        __syncthreads();
    }
    if (threadIdx.x == 0) g_partial[blockIdx.x] = sred[0];
}

__global__ void k_final(float* __restrict__ out) {
    __shared__ float sred[1024];
    int t = threadIdx.x;
    sred[t] = g_partial[t] + g_partial[t + 1024] + g_partial[t + 2048] + g_partial[t + 3072];
    __syncthreads();
    for (int s = 512; s > 0; s >>= 1) {
        if (t < s) sred[t] += sred[t + s];
        __syncthreads();
    }
    if (t == 0) out[0] = sred[0] * (1.0f / 4194304.0f);
}

// ---------------------------------------------------------------------------
extern "C" void kernel_launch(void* const* d_in, const int* in_sizes, int n_in,
                              void* d_out, int out_size) {
    const float* pred   = (const float*)d_in[0];
    const float* target = (const float*)d_in[1];
    const float* ref    = (const float*)d_in[2];
    float* out = (float*)d_out;

    const int blurSmem = 2 * IMG * (int)sizeof(float);            // 131072
    const int costSmem = 3 * SW * SP * (int)sizeof(float) + IMG;  // 214528
    cudaFuncSetAttribute(k_blur, cudaFuncAttributeMaxDynamicSharedMemorySize, blurSmem);
    cudaFuncSetAttribute(k_cost, cudaFuncAttributeMaxDynamicSharedMemorySize, costSmem);

    k_prepare<<<NPIX / 256, 256>>>(target, ref);   // launch 0
    k_blur<<<16, 256, blurSmem>>>(0, 0);           // launch 1 (prev imgs)
    k_blur<<<16, 256, blurSmem>>>(0, 16);          // launch 2 (curr imgs)
    k_cost<<<NB * 13, 512, costSmem>>>();          // launch 3  <- profiler slot
    k_blur<<<32, 256, blurSmem>>>(1, 0);           // launch 4 (flow blur, fused k_flow)
    k_loss<<<4096, 256>>>(pred, target, ref);      // launch 5
    k_final<<<1, 1024>>>(out);                     // launch 6
}

// round 4
// speedup vs baseline: 1.5397x; 1.2014x over previous
#include <cuda_runtime.h>

#define NB   16
#define FW   512
#define SW   128
#define IMG  (SW*SW)        // 16384
#define NPIX (NB*IMG)       // 262144
#define SP   129            // padded stride (prev/hsum)
#define CP   141            // padded stride for curr (140 cols used), odd -> conflict-free

// ---------------- device scratch (no cudaMalloc allowed) ----------------
__device__ float g_praw [2*NPIX];
__device__ float g_pblur[2*NPIX];
__device__ float g_rain [NPIX];
__device__ unsigned long long g_best[NPIX];
__device__ float g_flowb[2*NPIX];
__device__ float g_partial[4096];

__constant__ float GW[7] = {0.0044330482f, 0.0540055826f, 0.2420362293f,
                            0.3990502800f,
                            0.2420362293f, 0.0540055826f, 0.0044330482f};

// ---------------- K1: log1p + exact 4x downsample + rain -----------------
__global__ void k_prepare(const float* __restrict__ target, const float* __restrict__ ref) {
    int i = blockIdx.x * 256 + threadIdx.x;
    if (i >= NPIX) return;
    int b = i >> 14;
    int p = i & (IMG - 1);
    int y = p >> 7, x = p & 127;
    const float* tb = target + b * (FW * FW);
    const float* rb = ref    + b * (FW * FW);
    int o00 = (4 * y + 1) * FW + (4 * x + 1);
    float t00 = tb[o00], t01 = tb[o00 + 1], t10 = tb[o00 + FW], t11 = tb[o00 + FW + 1];
    float r00 = rb[o00], r01 = rb[o00 + 1], r10 = rb[o00 + FW], r11 = rb[o00 + FW + 1];
    float tm = 0.25f * (t00 + t01 + t10 + t11);
    g_rain[i] = (tm >= 0.1f) ? 1.0f : 0.0f;
    float cw = 0.25f * (log1pf(fmaxf(t00, 0.f)) + log1pf(fmaxf(t01, 0.f)) +
                        log1pf(fmaxf(t10, 0.f)) + log1pf(fmaxf(t11, 0.f)));
    float pw = 0.25f * (log1pf(fmaxf(r00, 0.f)) + log1pf(fmaxf(r01, 0.f)) +
                        log1pf(fmaxf(r10, 0.f)) + log1pf(fmaxf(r11, 0.f)));
    g_praw[i]        = pw;
    g_praw[NPIX + i] = cw;
    g_best[i] = ~0ull;
}

// ---------------- separable 7x7 blur (edge-replicate) --------------------
__global__ void k_blur(int mode, int imgBase) {
    extern __shared__ float s[];
    float* s_in = s;
    float* s_h  = s + IMG;
    int img = imgBase + blockIdx.x;
    float* out = (mode == 0 ? g_pblur : g_flowb) + img * IMG;
    if (mode == 0) {
        const float* in = g_praw + img * IMG;
        for (int i = threadIdx.x; i < IMG; i += blockDim.x) s_in[i] = in[i];
    } else {
        int gi0 = (img & 15) * IMG;
        bool isY = (img >= 16);
        for (int i = threadIdx.x; i < IMG; i += blockDim.x) {
            unsigned idx = (unsigned)(g_best[gi0 + i] & 0xffu);
            float rain = g_rain[gi0 + i];
            int dyi = (int)(idx / 13u);
            int dxi = (int)idx - dyi * 13;
            s_in[i] = (isY ? (float)(dyi - 6) : (float)(dxi - 6)) * rain;
        }
    }
    __syncthreads();
    for (int i = threadIdx.x; i < IMG; i += blockDim.x) {
        int y = i >> 7, x = i & 127;
        float a = 0.f;
        #pragma unroll
        for (int u = -3; u <= 3; u++) {
            int xc = min(max(x + u, 0), 127);
            a += GW[u + 3] * s_in[(y << 7) + xc];
        }
        s_h[i] = a;
    }
    __syncthreads();
    const float* rimg = g_rain + (img & 15) * IMG;
    for (int i = threadIdx.x; i < IMG; i += blockDim.x) {
        int y = i >> 7, x = i & 127;
        float a = 0.f;
        #pragma unroll
        for (int u = -3; u <= 3; u++) {
            int yc = min(max(y + u, 0), 127);
            a += GW[u + 3] * s_h[(yc << 7) + x];
        }
        if (mode) a *= rimg[i];
        out[i] = a;
    }
}

// ---------------- K2: patch cost + argmin, dx-split -----------------------
// block = (batch, dyi, dxhalf): 16*13*2 = 416 blocks, 512 threads
// smem: prev[128][129] | curr[128][141] (cols -6..133 clamped) |
//       hsum[148][129] (rows -10..137, pads zero) | u8 bestidx[128*128]
__global__ void __launch_bounds__(512) k_cost() {
    extern __shared__ float sm[];
    float* s_prev = sm;                          // 128*129
    float* s_curr = sm + SW * SP;                // 128*141
    float* s_hsum = sm + SW * SP + SW * CP;      // 148*129 (row r at (r+10)*SP)
    unsigned char* s_bi = (unsigned char*)(s_hsum + 148 * SP);

    int blk  = blockIdx.x;
    int b    = blk / 26;
    int r26  = blk - b * 26;
    int dyi  = r26 >> 1;
    int half = r26 & 1;
    int dy   = dyi - 6;
    int dx0  = half ? 7 : 0;
    int dx1  = half ? 13 : 7;
    int t    = threadIdx.x;

    const float* pb = g_pblur + b * IMG;
    const float* cb = g_pblur + NPIX + b * IMG;

    // load prev (plain) and curr (dy pre-applied, +-6 col halo, clamped)
    for (int i = t; i < IMG; i += 512) {
        int r = i >> 7, c = i & 127;
        s_prev[r * SP + c] = pb[i];
    }
    for (int i = t; i < SW * 140; i += 512) {
        int r = i / 140;
        int c = i - r * 140 - 6;                 // -6..133
        int rs = min(max(r + dy, 0), 127);
        int cs = min(max(c, 0), 127);
        s_curr[r * CP + (c + 6)] = cb[(rs << 7) + cs];
    }
    // zero hsum row pads: rows -10..-1 and 128..137
    for (int i = t; i < 20 * SW; i += 512) {
        int row = i >> 7;                        // 0..19
        int r = (row < 10) ? (row - 10) : (row + 118);
        s_hsum[(r + 10) * SP + (i & 127)] = 0.f;
    }
    __syncthreads();

    const int col  = t & 127;          // v-pass column
    const int rseg = (t >> 7) << 5;    // v-pass rows [rseg, rseg+32)
    const int hr   = t & 127;          // h-pass row
    const int hc0  = (t >> 7) << 5;    // h-pass cols [hc0, hc0+32)

    float bestc[32];
    #pragma unroll
    for (int k = 0; k < 32; k++) bestc[k] = 3.0e38f;

    #pragma unroll 1
    for (int dxi = dx0; dxi < dx1; dxi++) {
        int dx = dxi - 6;
        // ---- horizontal 21-window sliding sum of d^2 (zero-padded cols) ----
        {
            const float* pr = s_prev + hr * SP;
            const float* cr = s_curr + hr * CP + 6 + dx;   // cr[c] = curr[hr][clamp(c+dx)]
            float w = 0.f;
            #pragma unroll
            for (int u = -10; u <= 10; u++) {
                int c = hc0 + u;
                if ((unsigned)c < 128u) {          // warp-uniform
                    float d = pr[c] - cr[c];
                    w += d * d;
                }
            }
            float* hrow = s_hsum + (hr + 10) * SP;
            #pragma unroll 4
            for (int k = 0; k < 32; k++) {
                int c = hc0 + k;
                hrow[c] = w;
                int ca = c + 11;
                if (ca < 128) {                    // warp-uniform
                    float d = pr[ca] - cr[ca];
                    w += d * d;
                }
                int cs = c - 10;
                if (cs >= 0) {                     // warp-uniform
                    float d = pr[cs] - cr[cs];
                    w -= d * d;
                }
            }
        }
        __syncthreads();
        // ---- vertical 21-window sliding sum + running argmin (no bounds) ----
        {
            const float* hcp = s_hsum + 10 * SP + col;   // row r at hcp[r*SP]
            float w = 0.f;
            #pragma unroll
            for (int u = -10; u <= 10; u++) w += hcp[(rseg + u) * SP];
            unsigned char idx = (unsigned char)(dyi * 13 + dxi);
            #pragma unroll
            for (int k = 0; k < 32; k++) {
                if (w < bestc[k]) { bestc[k] = w; s_bi[((rseg + k) << 7) + col] = idx; }
                w += hcp[(rseg + k + 11) * SP];
                w -= hcp[(rseg + k - 10) * SP];
            }
        }
        __syncthreads();
    }
    // merge: packed (costbits<<32 | idx) atomicMin == first-index-tie argmin
    unsigned long long* gb = g_best + b * IMG;
    #pragma unroll 4
    for (int k = 0; k < 32; k++) {
        int r = rseg + k;
        unsigned long long key =
            ((unsigned long long)__float_as_uint(bestc[k]) << 32) |
            (unsigned long long)s_bi[(r << 7) + col];
        atomicMin(gb + (r << 7) + col, key);
    }
}

// ---------------- K4: upsample flow + warp ref + Huber + mask + reduce ----
__global__ void k_loss(const float* __restrict__ pred, const float* __restrict__ target,
                       const float* __restrict__ ref) {
    int idx4 = blockIdx.x * blockDim.x + threadIdx.x;
    int pix0 = idx4 << 2;
    int b  = pix0 >> 18;
    int p  = pix0 & 262143;
    int oy = p >> 9, ox0 = p & 511;

    float4 pv  = *reinterpret_cast<const float4*>(pred   + pix0);
    float4 tv4 = *reinterpret_cast<const float4*>(target + pix0);
    const float pr4[4] = {pv.x, pv.y, pv.z, pv.w};
    const float tg4[4] = {tv4.x, tv4.y, tv4.z, tv4.w};

    float sy = 0.25f * ((float)oy + 0.5f) - 0.5f; sy = fmaxf(sy, 0.f);
    int iy0 = (int)sy; float wy = sy - (float)iy0; int iy1 = min(iy0 + 1, 127);
    const float* fxp = g_flowb + b * IMG;
    const float* fyp = g_flowb + NPIX + b * IMG;
    const float* rb  = ref + b * (FW * FW);

    float acc = 0.f;
    #pragma unroll
    for (int j = 0; j < 4; j++) {
        int ox = ox0 + j;
        float sx = 0.25f * ((float)ox + 0.5f) - 0.5f; sx = fmaxf(sx, 0.f);
        int ix0 = (int)sx; float wx = sx - (float)ix0; int ix1 = min(ix0 + 1, 127);
        int o00 = (iy0 << 7) + ix0, o01 = (iy0 << 7) + ix1;
        int o10 = (iy1 << 7) + ix0, o11 = (iy1 << 7) + ix1;
        float w00 = (1.f - wy) * (1.f - wx), w01 = (1.f - wy) * wx;
        float w10 = wy * (1.f - wx),        w11 = wy * wx;
        float fx = (fxp[o00]*w00 + fxp[o01]*w01 + fxp[o10]*w10 + fxp[o11]*w11) * 4.0f;
        float fy = (fyp[o00]*w00 + fyp[o01]*w01 + fyp[o10]*w10 + fyp[o11]*w11) * 4.0f;
        float X = fminf(fmaxf((float)ox - fx, 0.f), 511.f);
        float Y = fminf(fmaxf((float)oy - fy, 0.f), 511.f);
        int x0 = (int)X; float ax = X - (float)x0; int x1 = min(x0 + 1, 511);
        int y0 = (int)Y; float ay = Y - (float)y0; int y1 = min(y0 + 1, 511);
        float v00 = rb[y0 * FW + x0], v01 = rb[y0 * FW + x1];
        float v10 = rb[y1 * FW + x0], v11 = rb[y1 * FW + x1];
        float tv = v00 * (1.f - ay) * (1.f - ax) + v01 * (1.f - ay) * ax +
                   v10 * ay * (1.f - ax)         + v11 * ay * ax;
        float teacher = fmaxf(tv, 0.f);
        float d  = pr4[j] - teacher;
        float ad = fabsf(d);
        float l  = (ad < 0.2f) ? (0.5f * d * d) : (0.2f * (ad - 0.1f));
        float m  = (teacher > 0.05f || tg4[j] > 0.05f) ? 1.f : 0.f;
        acc += l * m;
    }
    __shared__ float sred[256];
    sred[threadIdx.x] = acc;
    __syncthreads();
    for (int s = 128; s > 0; s >>= 1) {
        if (threadIdx.x < s) sred[threadIdx.x] += sred[threadIdx.x + s];
        __syncthreads();
    }
    if (threadIdx.x == 0) g_partial[blockIdx.x] = sred[0];
}

__global__ void k_final(float* __restrict__ out) {
    __shared__ float sred[1024];
    int t = threadIdx.x;
    sred[t] = g_partial[t] + g_partial[t + 1024] + g_partial[t + 2048] + g_partial[t + 3072];
    __syncthreads();
    for (int s = 512; s > 0; s >>= 1) {
        if (t < s) sred[t] += sred[t + s];
        __syncthreads();
    }
    if (t == 0) out[0] = sred[0] * (1.0f / 4194304.0f);
}

// ---------------------------------------------------------------------------
extern "C" void kernel_launch(void* const* d_in, const int* in_sizes, int n_in,
                              void* d_out, int out_size) {
    const float* pred   = (const float*)d_in[0];
    const float* target = (const float*)d_in[1];
    const float* ref    = (const float*)d_in[2];
    float* out = (float*)d_out;

    const int blurSmem = 2 * IMG * (int)sizeof(float);
    const int costSmem = (SW * SP + SW * CP + 148 * SP) * (int)sizeof(float) + IMG; // 230992
    cudaFuncSetAttribute(k_blur, cudaFuncAttributeMaxDynamicSharedMemorySize, blurSmem);
    cudaFuncSetAttribute(k_cost, cudaFuncAttributeMaxDynamicSharedMemorySize, costSmem);

    k_prepare<<<NPIX / 256, 256>>>(target, ref);   // launch 0
    k_blur<<<16, 256, blurSmem>>>(0, 0);           // launch 1
    k_blur<<<16, 256, blurSmem>>>(0, 16);          // launch 2
    k_cost<<<NB * 13 * 2, 512, costSmem>>>();      // launch 3  <- profiler slot
    k_blur<<<32, 256, blurSmem>>>(1, 0);           // launch 4
    k_loss<<<4096, 256>>>(pred, target, ref);      // launch 5
    k_final<<<1, 1024>>>(out);                     // launch 6
}

// round 5
// speedup vs baseline: 2.0939x; 1.3599x over previous
#include <cuda_runtime.h>

#define NB   16
#define FW   512
#define SW   128
#define IMG  (SW*SW)        // 16384
#define NPIX (NB*IMG)       // 262144
#define SP   129            // padded stride (prev/hsum)
#define CP   141            // padded stride for curr (140 cols used)

// ---------------- device scratch (no cudaMalloc allowed) ----------------
__device__ float g_praw [2*NPIX];
__device__ float g_pblur[2*NPIX];
__device__ float g_rain [NPIX];
__device__ unsigned g_best[NPIX];    // packed (costbits & ~0xFF) | shiftIdx
__device__ float g_flowb[2*NPIX];
__device__ float g_partial[4096];

__constant__ float GW[7] = {0.0044330482f, 0.0540055826f, 0.2420362293f,
                            0.3990502800f,
                            0.2420362293f, 0.0540055826f, 0.0044330482f};

// ---------------- K1: log1p + exact 4x downsample + rain -----------------
__global__ void k_prepare(const float* __restrict__ target, const float* __restrict__ ref) {
    int i = blockIdx.x * 256 + threadIdx.x;
    if (i >= NPIX) return;
    int b = i >> 14;
    int p = i & (IMG - 1);
    int y = p >> 7, x = p & 127;
    const float* tb = target + b * (FW * FW);
    const float* rb = ref    + b * (FW * FW);
    int o00 = (4 * y + 1) * FW + (4 * x + 1);
    float t00 = tb[o00], t01 = tb[o00 + 1], t10 = tb[o00 + FW], t11 = tb[o00 + FW + 1];
    float r00 = rb[o00], r01 = rb[o00 + 1], r10 = rb[o00 + FW], r11 = rb[o00 + FW + 1];
    float tm = 0.25f * (t00 + t01 + t10 + t11);
    g_rain[i] = (tm >= 0.1f) ? 1.0f : 0.0f;
    float cw = 0.25f * (log1pf(fmaxf(t00, 0.f)) + log1pf(fmaxf(t01, 0.f)) +
                        log1pf(fmaxf(t10, 0.f)) + log1pf(fmaxf(t11, 0.f)));
    float pw = 0.25f * (log1pf(fmaxf(r00, 0.f)) + log1pf(fmaxf(r01, 0.f)) +
                        log1pf(fmaxf(r10, 0.f)) + log1pf(fmaxf(r11, 0.f)));
    g_praw[i]        = pw;
    g_praw[NPIX + i] = cw;
    g_best[i] = 0xFFFFFFFFu;
}

// ---------------- separable 7x7 blur, strip-parallel (4 strips/img) ------
// block = (img, strip). mode 0: g_praw -> g_pblur. mode 1: flow decode -> g_flowb (*rain)
__global__ void __launch_bounds__(256) k_blur(int mode, int imgBase) {
    __shared__ float s_in[38 * 128];
    __shared__ float s_h [38 * 128];
    int img  = imgBase + (blockIdx.x >> 2);
    int s    = blockIdx.x & 3;
    int rbase = 32 * s - 3;
    float* out = (mode == 0 ? g_pblur : g_flowb) + img * IMG + 32 * s * 128;

    if (mode == 0) {
        const float* in = g_praw + img * IMG;
        for (int i = threadIdx.x; i < 38 * 128; i += 256) {
            int lr = i >> 7;
            int gr = min(max(rbase + lr, 0), 127);
            s_in[i] = in[(gr << 7) + (i & 127)];
        }
    } else {
        int gi0 = (img & 15) * IMG;
        bool isY = (img >= 16);
        for (int i = threadIdx.x; i < 38 * 128; i += 256) {
            int lr = i >> 7;
            int gr = min(max(rbase + lr, 0), 127);
            int gidx = gi0 + (gr << 7) + (i & 127);
            unsigned idx = g_best[gidx] & 0xFFu;
            float rain = g_rain[gidx];
            int dyi = (int)(idx / 13u);
            int dxi = (int)idx - dyi * 13;
            s_in[i] = (isY ? (float)(dyi - 6) : (float)(dxi - 6)) * rain;
        }
    }
    __syncthreads();
    for (int i = threadIdx.x; i < 38 * 128; i += 256) {
        int x = i & 127;
        int lr7 = i - x;
        float a = 0.f;
        #pragma unroll
        for (int u = -3; u <= 3; u++) {
            int xc = min(max(x + u, 0), 127);
            a += GW[u + 3] * s_in[lr7 + xc];
        }
        s_h[i] = a;
    }
    __syncthreads();
    const float* rimg = g_rain + (img & 15) * IMG + 32 * s * 128;
    for (int i = threadIdx.x; i < 32 * 128; i += 256) {
        int j = i >> 7, x = i & 127;
        float a = 0.f;
        #pragma unroll
        for (int u = -3; u <= 3; u++)
            a += GW[u + 3] * s_h[((j + 3 + u) << 7) + x];   // halo rows already replicate-correct
        if (mode) a *= rimg[i];
        out[i] = a;
    }
}

// ---------------- K2: patch cost + argmin, 1024 threads -------------------
// block = (batch, dyi, dxhalf): 416 blocks, 1024 threads (32 warps/SM)
// smem: prev[128][129] | curr[128][141] | hsum[148][129] (rows -10..137, pads zero)
__global__ void __launch_bounds__(1024) k_cost() {
    extern __shared__ float sm[];
    float* s_prev = sm;
    float* s_curr = sm + SW * SP;
    float* s_hsum = sm + SW * SP + SW * CP;   // global row r at local (r+10)*SP

    int blk  = blockIdx.x;
    int b    = blk / 26;
    int r26  = blk - b * 26;
    int dyi  = r26 >> 1;
    int half = r26 & 1;
    int dy   = dyi - 6;
    int dx0  = half ? 7 : 0;
    int dx1  = half ? 13 : 7;
    int t    = threadIdx.x;

    const float* pb = g_pblur + b * IMG;
    const float* cb = g_pblur + NPIX + b * IMG;

    for (int i = t; i < IMG; i += 1024) {
        int r = i >> 7, c = i & 127;
        s_prev[r * SP + c] = pb[i];
    }
    for (int i = t; i < SW * 140; i += 1024) {
        int r = i / 140;
        int c = i - r * 140 - 6;                 // -6..133
        int rs = min(max(r + dy, 0), 127);
        int cs = min(max(c, 0), 127);
        s_curr[r * CP + (c + 6)] = cb[(rs << 7) + cs];
    }
    for (int i = t; i < 20 * SW; i += 1024) {
        int row = i >> 7;                        // 0..19
        int lr = (row < 10) ? row : (row + 128); // local pad rows 0..9, 138..147
        s_hsum[lr * SP + (i & 127)] = 0.f;
    }
    __syncthreads();

    const int hr  = t & 127;           // h-pass row (lane-consecutive -> conflict-free)
    const int hc0 = (t >> 7) << 4;     // h-pass cols [hc0, hc0+16)
    const int col = t & 127;           // v-pass column
    const int r0  = (t >> 7) << 4;     // v-pass rows [r0, r0+16)

    unsigned kmin[16];
    #pragma unroll
    for (int k = 0; k < 16; k++) kmin[k] = 0xFFFFFFFFu;

    #pragma unroll 1
    for (int dxi = dx0; dxi < dx1; dxi++) {
        int dx = dxi - 6;
        // ---- horizontal 21-window sliding sum of d^2 (zero-pad window cols) ----
        {
            const float* pr = s_prev + hr * SP;
            const float* cr = s_curr + hr * CP + 6 + dx;   // cr[c] = curr[hr][clamp(c+dx)]
            float w = 0.f;
            #pragma unroll
            for (int u = -10; u <= 10; u++) {
                int c = hc0 + u;
                if ((unsigned)c < 128u) { float d = pr[c] - cr[c]; w += d * d; }
            }
            float* hrow = s_hsum + (hr + 10) * SP;
            #pragma unroll
            for (int k = 0; k < 16; k++) {
                int c = hc0 + k;
                hrow[c] = w;
                if (k < 15) {
                    int ca = c + 11;
                    if (ca < 128) { float d = pr[ca] - cr[ca]; w += d * d; }
                    int cs2 = c - 10;
                    if (cs2 >= 0) { float d = pr[cs2] - cr[cs2]; w -= d * d; }
                }
            }
        }
        __syncthreads();
        // ---- vertical 21-window sliding sum + packed-key running min ----
        {
            const float* hcp = s_hsum + 10 * SP + col;
            float w = 0.f;
            #pragma unroll
            for (int u = -10; u <= 10; u++) w += hcp[(r0 + u) * SP];
            unsigned idx = (unsigned)(dyi * 13 + dxi);
            #pragma unroll
            for (int k = 0; k < 16; k++) {
                unsigned key = (__float_as_uint(w) & 0xFFFFFF00u) | idx;
                kmin[k] = min(kmin[k], key);
                if (k < 15) {
                    w += hcp[(r0 + k + 11) * SP];
                    w -= hcp[(r0 + k - 10) * SP];
                }
            }
        }
        __syncthreads();
    }
    unsigned* gb = g_best + b * IMG;
    #pragma unroll
    for (int k = 0; k < 16; k++)
        atomicMin(gb + ((r0 + k) << 7) + col, kmin[k]);
}

// ---------------- K4: upsample flow + warp ref + Huber + mask + reduce ----
__global__ void k_loss(const float* __restrict__ pred, const float* __restrict__ target,
                       const float* __restrict__ ref) {
    int idx4 = blockIdx.x * blockDim.x + threadIdx.x;
    int pix0 = idx4 << 2;
    int b  = pix0 >> 18;
    int p  = pix0 & 262143;
    int oy = p >> 9, ox0 = p & 511;

    float4 pv  = *reinterpret_cast<const float4*>(pred   + pix0);
    float4 tv4 = *reinterpret_cast<const float4*>(target + pix0);
    const float pr4[4] = {pv.x, pv.y, pv.z, pv.w};
    const float tg4[4] = {tv4.x, tv4.y, tv4.z, tv4.w};

    float sy = 0.25f * ((float)oy + 0.5f) - 0.5f; sy = fmaxf(sy, 0.f);
    int iy0 = (int)sy; float wy = sy - (float)iy0; int iy1 = min(iy0 + 1, 127);
    const float* fxp = g_flowb + b * IMG;
    const float* fyp = g_flowb + NPIX + b * IMG;
    const float* rb  = ref + b * (FW * FW);

    float acc = 0.f;
    #pragma unroll
    for (int j = 0; j < 4; j++) {
        int ox = ox0 + j;
        float sx = 0.25f * ((float)ox + 0.5f) - 0.5f; sx = fmaxf(sx, 0.f);
        int ix0 = (int)sx; float wx = sx - (float)ix0; int ix1 = min(ix0 + 1, 127);
        int o00 = (iy0 << 7) + ix0, o01 = (iy0 << 7) + ix1;
        int o10 = (iy1 << 7) + ix0, o11 = (iy1 << 7) + ix1;
        float w00 = (1.f - wy) * (1.f - wx), w01 = (1.f - wy) * wx;
        float w10 = wy * (1.f - wx),        w11 = wy * wx;
        float fx = (fxp[o00]*w00 + fxp[o01]*w01 + fxp[o10]*w10 + fxp[o11]*w11) * 4.0f;
        float fy = (fyp[o00]*w00 + fyp[o01]*w01 + fyp[o10]*w10 + fyp[o11]*w11) * 4.0f;
        float X = fminf(fmaxf((float)ox - fx, 0.f), 511.f);
        float Y = fminf(fmaxf((float)oy - fy, 0.f), 511.f);
        int x0 = (int)X; float ax = X - (float)x0; int x1 = min(x0 + 1, 511);
        int y0 = (int)Y; float ay = Y - (float)y0; int y1 = min(y0 + 1, 511);
        float v00 = rb[y0 * FW + x0], v01 = rb[y0 * FW + x1];
        float v10 = rb[y1 * FW + x0], v11 = rb[y1 * FW + x1];
        float tv = v00 * (1.f - ay) * (1.f - ax) + v01 * (1.f - ay) * ax +
                   v10 * ay * (1.f - ax)         + v11 * ay * ax;
        float teacher = fmaxf(tv, 0.f);
        float d  = pr4[j] - teacher;
        float ad = fabsf(d);
        float l  = (ad < 0.2f) ? (0.5f * d * d) : (0.2f * (ad - 0.1f));
        float m  = (teacher > 0.05f || tg4[j] > 0.05f) ? 1.f : 0.f;
        acc += l * m;
    }
    __shared__ float sred[256];
    sred[threadIdx.x] = acc;
    __syncthreads();
    for (int s = 128; s > 0; s >>= 1) {
        if (threadIdx.x < s) sred[threadIdx.x] += sred[threadIdx.x + s];
        __syncthreads();
    }
    if (threadIdx.x == 0) g_partial[blockIdx.x] = sred[0];
}

__global__ void k_final(float* __restrict__ out) {
    __shared__ float sred[1024];
    int t = threadIdx.x;
    sred[t] = g_partial[t] + g_partial[t + 1024] + g_partial[t + 2048] + g_partial[t + 3072];
    __syncthreads();
    for (int s = 512; s > 0; s >>= 1) {
        if (t < s) sred[t] += sred[t + s];
        __syncthreads();
    }
    if (t == 0) out[0] = sred[0] * (1.0f / 4194304.0f);
}

// ---------------------------------------------------------------------------
extern "C" void kernel_launch(void* const* d_in, const int* in_sizes, int n_in,
                              void* d_out, int out_size) {
    const float* pred   = (const float*)d_in[0];
    const float* target = (const float*)d_in[1];
    const float* ref    = (const float*)d_in[2];
    float* out = (float*)d_out;

    const int costSmem = (SW * SP + SW * CP + 148 * SP) * (int)sizeof(float); // 214608
    cudaFuncSetAttribute(k_cost, cudaFuncAttributeMaxDynamicSharedMemorySize, costSmem);

    k_prepare<<<NPIX / 256, 256>>>(target, ref);   // launch 0
    k_blur<<<64, 256>>>(0, 0);                     // launch 1 (prev imgs, 16x4 strips)
    k_blur<<<64, 256>>>(0, 16);                    // launch 2 (curr imgs)
    k_cost<<<NB * 13 * 2, 1024, costSmem>>>();     // launch 3  <- profiler slot
    k_blur<<<128, 256>>>(1, 0);                    // launch 4 (flow decode + blur)
    k_loss<<<4096, 256>>>(pred, target, ref);      // launch 5
    k_final<<<1, 1024>>>(out);                     // launch 6
}

// round 6
// speedup vs baseline: 2.4776x; 1.1833x over previous
#include <cuda_runtime.h>

#define NB   16
#define FW   512
#define SW   128
#define IMG  (SW*SW)        // 16384
#define NPIX (NB*IMG)       // 262144
#define CSTR 141            // s_curr stride (gcd(141,32)=1, scalar conflict-free)
#define PSTR 132            // s_prev stride (4i chunk pattern, float4 conflict-free)
#define TSTR 148            // s_hsumT stride (20i chunk pattern, float4 conflict-free)

// ---------------- device scratch (no cudaMalloc allowed) ----------------
__device__ float g_praw [2*NPIX];
__device__ float g_pblur[2*NPIX];
__device__ float g_rain [NPIX];
__device__ unsigned g_best[NPIX];    // packed (costbits & ~0xFF) | shiftIdx
__device__ float g_flowb[2*NPIX];
__device__ float g_partial[4096];

__constant__ float GW[7] = {0.0044330482f, 0.0540055826f, 0.2420362293f,
                            0.3990502800f,
                            0.2420362293f, 0.0540055826f, 0.0044330482f};

// ---------------- K1: log1p + exact 4x downsample + rain -----------------
__global__ void k_prepare(const float* __restrict__ target, const float* __restrict__ ref) {
    int i = blockIdx.x * 256 + threadIdx.x;
    if (i >= NPIX) return;
    int b = i >> 14;
    int p = i & (IMG - 1);
    int y = p >> 7, x = p & 127;
    const float* tb = target + b * (FW * FW);
    const float* rb = ref    + b * (FW * FW);
    int o00 = (4 * y + 1) * FW + (4 * x + 1);
    float t00 = tb[o00], t01 = tb[o00 + 1], t10 = tb[o00 + FW], t11 = tb[o00 + FW + 1];
    float r00 = rb[o00], r01 = rb[o00 + 1], r10 = rb[o00 + FW], r11 = rb[o00 + FW + 1];
    float tm = 0.25f * (t00 + t01 + t10 + t11);
    g_rain[i] = (tm >= 0.1f) ? 1.0f : 0.0f;
    float cw = 0.25f * (log1pf(fmaxf(t00, 0.f)) + log1pf(fmaxf(t01, 0.f)) +
                        log1pf(fmaxf(t10, 0.f)) + log1pf(fmaxf(t11, 0.f)));
    float pw = 0.25f * (log1pf(fmaxf(r00, 0.f)) + log1pf(fmaxf(r01, 0.f)) +
                        log1pf(fmaxf(r10, 0.f)) + log1pf(fmaxf(r11, 0.f)));
    g_praw[i]        = pw;
    g_praw[NPIX + i] = cw;
    g_best[i] = 0xFFFFFFFFu;
}

// ---------------- separable 7x7 blur, strip-parallel (4 strips/img) ------
__global__ void __launch_bounds__(256) k_blur(int mode, int imgBase) {
    __shared__ float s_in[38 * 128];
    __shared__ float s_h [38 * 128];
    int img  = imgBase + (blockIdx.x >> 2);
    int s    = blockIdx.x & 3;
    int rbase = 32 * s - 3;
    float* out = (mode == 0 ? g_pblur : g_flowb) + img * IMG + 32 * s * 128;

    if (mode == 0) {
        const float* in = g_praw + img * IMG;
        for (int i = threadIdx.x; i < 38 * 128; i += 256) {
            int lr = i >> 7;
            int gr = min(max(rbase + lr, 0), 127);
            s_in[i] = in[(gr << 7) + (i & 127)];
        }
    } else {
        int gi0 = (img & 15) * IMG;
        bool isY = (img >= 16);
        for (int i = threadIdx.x; i < 38 * 128; i += 256) {
            int lr = i >> 7;
            int gr = min(max(rbase + lr, 0), 127);
            int gidx = gi0 + (gr << 7) + (i & 127);
            unsigned idx = g_best[gidx] & 0xFFu;
            float rain = g_rain[gidx];
            int dyi = (int)(idx / 13u);
            int dxi = (int)idx - dyi * 13;
            s_in[i] = (isY ? (float)(dyi - 6) : (float)(dxi - 6)) * rain;
        }
    }
    __syncthreads();
    for (int i = threadIdx.x; i < 38 * 128; i += 256) {
        int x = i & 127;
        int lr7 = i - x;
        float a = 0.f;
        #pragma unroll
        for (int u = -3; u <= 3; u++) {
            int xc = min(max(x + u, 0), 127);
            a += GW[u + 3] * s_in[lr7 + xc];
        }
        s_h[i] = a;
    }
    __syncthreads();
    const float* rimg = g_rain + (img & 15) * IMG + 32 * s * 128;
    for (int i = threadIdx.x; i < 32 * 128; i += 256) {
        int j = i >> 7, x = i & 127;
        float a = 0.f;
        #pragma unroll
        for (int u = -3; u <= 3; u++)
            a += GW[u + 3] * s_h[((j + 3 + u) << 7) + x];
        if (mode) a *= rimg[i];
        out[i] = a;
    }
}

// ---------------- K2: patch cost + argmin (register sliding windows) ------
// block = (batch, dyi, dxhalf): 416 blocks, 512 threads
// smem: s_curr[128][141] | s_prev[128][132] | s_hsumT[128][148] (transposed,
//       row rr=r+10, pad rows 0..9 & 138..147 zeroed once)
__global__ void __launch_bounds__(512) k_cost() {
    extern __shared__ float sm[];
    float* s_curr  = sm;                         // placed first so s_prev-12 underflow
    float* s_prev  = sm + SW * CSTR;             //   lands in s_curr (harmless, masked)
    float* s_hsumT = sm + SW * CSTR + SW * PSTR; //   and +tail overflow lands here

    int blk  = blockIdx.x;
    int b    = blk / 26;
    int r26  = blk - b * 26;
    int dyi  = r26 >> 1;
    int half = r26 & 1;
    int dy   = dyi - 6;
    int dx0  = half ? 7 : 0;
    int dx1  = half ? 13 : 7;
    int t    = threadIdx.x;

    const float* pb = g_pblur + b * IMG;
    const float* cb = g_pblur + NPIX + b * IMG;

    for (int i = t; i < IMG; i += 512) {
        int r = i >> 7, c = i & 127;
        s_prev[r * PSTR + c] = pb[i];
    }
    for (int i = t; i < SW * 140; i += 512) {
        int r = i / 140;
        int c = i - r * 140 - 6;                 // -6..133
        int rs = min(max(r + dy, 0), 127);
        int cs = min(max(c, 0), 127);
        s_curr[r * CSTR + (c + 6)] = cb[(rs << 7) + cs];
    }
    for (int i = t; i < 20 * SW; i += 512) {
        int row = i >> 7;                        // 0..19
        int rr = (row < 10) ? row : (row + 128); // pad rows 0..9, 138..147
        s_hsumT[(i & 127) * TSTR + rr] = 0.f;
    }
    __syncthreads();

    const int hr  = t & 127;           // h-pass row
    const int hc0 = (t >> 7) << 5;     // h-pass cols [hc0, hc0+32)
    const int col = t & 127;           // v-pass column
    const int r0  = (t >> 7) << 5;     // v-pass rows [r0, r0+32)

    unsigned kmin[32];
    #pragma unroll
    for (int k = 0; k < 32; k++) kmin[k] = 0xFFFFFFFFu;

    #pragma unroll 1
    for (int dxi = dx0; dxi < dx1; dxi++) {
        int dx = dxi - 6;
        // ---- h-pass: prev window in regs (14x LDS.128), curr scalar ----
        {
            float p[56];
            const float4* pv = reinterpret_cast<const float4*>(s_prev + hr * PSTR + hc0 - 12);
            #pragma unroll
            for (int j = 0; j < 14; j++) {
                float4 q = pv[j];
                p[4*j] = q.x; p[4*j+1] = q.y; p[4*j+2] = q.z; p[4*j+3] = q.w;
            }
            const float* cr = s_curr + hr * CSTR + 6 + dx;   // cr[c] = curr[hr][clamp(c+dx)]
            float* hT = s_hsumT + hr + 10;                   // store hsumT[c][hr+10]

            float w = 0.f;
            #pragma unroll
            for (int u = -10; u <= 10; u++) {
                int c = hc0 + u;
                if ((unsigned)c < 128u) { float d = p[u + 12] - cr[c]; w += d * d; }
            }
            #pragma unroll
            for (int k = 0; k < 32; k++) {
                int c = hc0 + k;
                hT[c * TSTR] = w;
                if (k < 31) {
                    int ca = c + 11;
                    if (ca < 128) { float d = p[k + 23] - cr[ca]; w += d * d; }
                    int cs2 = c - 10;
                    if (cs2 >= 0) { float d = p[k + 2] - cr[cs2]; w -= d * d; }
                }
            }
        }
        __syncthreads();
        // ---- v-pass: column window in regs (13x LDS.128), reg sliding ----
        {
            float v[52];
            const float4* hv = reinterpret_cast<const float4*>(s_hsumT + col * TSTR + r0);
            #pragma unroll
            for (int j = 0; j < 13; j++) {
                float4 q = hv[j];
                v[4*j] = q.x; v[4*j+1] = q.y; v[4*j+2] = q.z; v[4*j+3] = q.w;
            }
            float w = 0.f;
            #pragma unroll
            for (int j = 0; j < 21; j++) w += v[j];
            unsigned idx = (unsigned)(dyi * 13 + dxi);
            #pragma unroll
            for (int k = 0; k < 32; k++) {
                unsigned key = (__float_as_uint(w) & 0xFFFFFF00u) | idx;
                kmin[k] = min(kmin[k], key);
                if (k < 31) { w += v[k + 21]; w -= v[k]; }
            }
        }
        __syncthreads();
    }
    unsigned* gb = g_best + b * IMG;
    #pragma unroll
    for (int k = 0; k < 32; k++)
        atomicMin(gb + ((r0 + k) << 7) + col, kmin[k]);
}

// ---------------- K4: upsample flow + warp ref + Huber + mask + reduce ----
__global__ void k_loss(const float* __restrict__ pred, const float* __restrict__ target,
                       const float* __restrict__ ref) {
    int idx4 = blockIdx.x * blockDim.x + threadIdx.x;
    int pix0 = idx4 << 2;
    int b  = pix0 >> 18;
    int p  = pix0 & 262143;
    int oy = p >> 9, ox0 = p & 511;

    float4 pv  = *reinterpret_cast<const float4*>(pred   + pix0);
    float4 tv4 = *reinterpret_cast<const float4*>(target + pix0);
    const float pr4[4] = {pv.x, pv.y, pv.z, pv.w};
    const float tg4[4] = {tv4.x, tv4.y, tv4.z, tv4.w};

    float sy = 0.25f * ((float)oy + 0.5f) - 0.5f; sy = fmaxf(sy, 0.f);
    int iy0 = (int)sy; float wy = sy - (float)iy0; int iy1 = min(iy0 + 1, 127);
    const float* fxp = g_flowb + b * IMG;
    const float* fyp = g_flowb + NPIX + b * IMG;
    const float* rb  = ref + b * (FW * FW);

    float acc = 0.f;
    #pragma unroll
    for (int j = 0; j < 4; j++) {
        int ox = ox0 + j;
        float sx = 0.25f * ((float)ox + 0.5f) - 0.5f; sx = fmaxf(sx, 0.f);
        int ix0 = (int)sx; float wx = sx - (float)ix0; int ix1 = min(ix0 + 1, 127);
        int o00 = (iy0 << 7) + ix0, o01 = (iy0 << 7) + ix1;
        int o10 = (iy1 << 7) + ix0, o11 = (iy1 << 7) + ix1;
        float w00 = (1.f - wy) * (1.f - wx), w01 = (1.f - wy) * wx;
        float w10 = wy * (1.f - wx),        w11 = wy * wx;
        float fx = (fxp[o00]*w00 + fxp[o01]*w01 + fxp[o10]*w10 + fxp[o11]*w11) * 4.0f;
        float fy = (fyp[o00]*w00 + fyp[o01]*w01 + fyp[o10]*w10 + fyp[o11]*w11) * 4.0f;
        float X = fminf(fmaxf((float)ox - fx, 0.f), 511.f);
        float Y = fminf(fmaxf((float)oy - fy, 0.f), 511.f);
        int x0 = (int)X; float ax = X - (float)x0; int x1 = min(x0 + 1, 511);
        int y0 = (int)Y; float ay = Y - (float)y0; int y1 = min(y0 + 1, 511);
        float v00 = rb[y0 * FW + x0], v01 = rb[y0 * FW + x1];
        float v10 = rb[y1 * FW + x0], v11 = rb[y1 * FW + x1];
        float tv = v00 * (1.f - ay) * (1.f - ax) + v01 * (1.f - ay) * ax +
                   v10 * ay * (1.f - ax)         + v11 * ay * ax;
        float teacher = fmaxf(tv, 0.f);
        float d  = pr4[j] - teacher;
        float ad = fabsf(d);
        float l  = (ad < 0.2f) ? (0.5f * d * d) : (0.2f * (ad - 0.1f));
        float m  = (teacher > 0.05f || tg4[j] > 0.05f) ? 1.f : 0.f;
        acc += l * m;
    }
    __shared__ float sred[256];
    sred[threadIdx.x] = acc;
    __syncthreads();
    for (int s = 128; s > 0; s >>= 1) {
        if (threadIdx.x < s) sred[threadIdx.x] += sred[threadIdx.x + s];
        __syncthreads();
    }
    if (threadIdx.x == 0) g_partial[blockIdx.x] = sred[0];
}

__global__ void k_final(float* __restrict__ out) {
    __shared__ float sred[1024];
    int t = threadIdx.x;
    sred[t] = g_partial[t] + g_partial[t + 1024] + g_partial[t + 2048] + g_partial[t + 3072];
    __syncthreads();
    for (int s = 512; s > 0; s >>= 1) {
        if (t < s) sred[t] += sred[t + s];
        __syncthreads();
    }
    if (t == 0) out[0] = sred[0] * (1.0f / 4194304.0f);
}

// ---------------------------------------------------------------------------
extern "C" void kernel_launch(void* const* d_in, const int* in_sizes, int n_in,
                              void* d_out, int out_size) {
    const float* pred   = (const float*)d_in[0];
    const float* target = (const float*)d_in[1];
    const float* ref    = (const float*)d_in[2];
    float* out = (float*)d_out;

    const int costSmem = SW * (CSTR + PSTR + TSTR) * (int)sizeof(float); // 215552
    cudaFuncSetAttribute(k_cost, cudaFuncAttributeMaxDynamicSharedMemorySize, costSmem);

    k_prepare<<<NPIX / 256, 256>>>(target, ref);   // launch 0
    k_blur<<<64, 256>>>(0, 0);                     // launch 1
    k_blur<<<64, 256>>>(0, 16);                    // launch 2
    k_cost<<<NB * 13 * 2, 512, costSmem>>>();      // launch 3  <- profiler slot
    k_blur<<<128, 256>>>(1, 0);                    // launch 4
    k_loss<<<4096, 256>>>(pred, target, ref);      // launch 5
    k_final<<<1, 1024>>>(out);                     // launch 6
}

// round 7
// speedup vs baseline: 2.6064x; 1.0520x over previous
#include <cuda_runtime.h>

#define NB   16
#define FW   512
#define SW   128
#define IMG  (SW*SW)        // 16384
#define NPIX (NB*IMG)       // 262144
#define CSTR 141            // s_curr stride (scalar conflict-free)
#define PSTR 132            // s_prev stride (float4 conflict-free, 4i pattern)
#define TSTR 156            // s_hsumT stride (float4 conflict-free: 156/4=39 odd)

// ---------------- device scratch (no cudaMalloc allowed) ----------------
__device__ float g_praw [2*NPIX];
__device__ float g_pblur[2*NPIX];
__device__ float g_rain [NPIX];
__device__ unsigned g_best[NPIX];    // packed (costbits & ~0xFF) | shiftIdx
__device__ float g_flowb[2*NPIX];
__device__ float g_partial[4096];

__constant__ float GW[7] = {0.0044330482f, 0.0540055826f, 0.2420362293f,
                            0.3990502800f,
                            0.2420362293f, 0.0540055826f, 0.0044330482f};

// ---------------- K1: log1p + exact 4x downsample + rain -----------------
__global__ void k_prepare(const float* __restrict__ target, const float* __restrict__ ref) {
    int i = blockIdx.x * 256 + threadIdx.x;
    if (i >= NPIX) return;
    int b = i >> 14;
    int p = i & (IMG - 1);
    int y = p >> 7, x = p & 127;
    const float* tb = target + b * (FW * FW);
    const float* rb = ref    + b * (FW * FW);
    int o00 = (4 * y + 1) * FW + (4 * x + 1);
    float t00 = tb[o00], t01 = tb[o00 + 1], t10 = tb[o00 + FW], t11 = tb[o00 + FW + 1];
    float r00 = rb[o00], r01 = rb[o00 + 1], r10 = rb[o00 + FW], r11 = rb[o00 + FW + 1];
    float tm = 0.25f * (t00 + t01 + t10 + t11);
    g_rain[i] = (tm >= 0.1f) ? 1.0f : 0.0f;
    float cw = 0.25f * (log1pf(fmaxf(t00, 0.f)) + log1pf(fmaxf(t01, 0.f)) +
                        log1pf(fmaxf(t10, 0.f)) + log1pf(fmaxf(t11, 0.f)));
    float pw = 0.25f * (log1pf(fmaxf(r00, 0.f)) + log1pf(fmaxf(r01, 0.f)) +
                        log1pf(fmaxf(r10, 0.f)) + log1pf(fmaxf(r11, 0.f)));
    g_praw[i]        = pw;
    g_praw[NPIX + i] = cw;
    g_best[i] = 0xFFFFFFFFu;
}

// ---------------- separable 7x7 blur, strip-parallel (4 strips/img) ------
__global__ void __launch_bounds__(256) k_blur(int mode, int imgBase) {
    __shared__ float s_in[38 * 128];
    __shared__ float s_h [38 * 128];
    int img  = imgBase + (blockIdx.x >> 2);
    int s    = blockIdx.x & 3;
    int rbase = 32 * s - 3;
    float* out = (mode == 0 ? g_pblur : g_flowb) + img * IMG + 32 * s * 128;

    if (mode == 0) {
        const float* in = g_praw + img * IMG;
        for (int i = threadIdx.x; i < 38 * 128; i += 256) {
            int lr = i >> 7;
            int gr = min(max(rbase + lr, 0), 127);
            s_in[i] = in[(gr << 7) + (i & 127)];
        }
    } else {
        int gi0 = (img & 15) * IMG;
        bool isY = (img >= 16);
        for (int i = threadIdx.x; i < 38 * 128; i += 256) {
            int lr = i >> 7;
            int gr = min(max(rbase + lr, 0), 127);
            int gidx = gi0 + (gr << 7) + (i & 127);
            unsigned idx = g_best[gidx] & 0xFFu;
            float rain = g_rain[gidx];
            int dyi = (int)(idx / 13u);
            int dxi = (int)idx - dyi * 13;
            s_in[i] = (isY ? (float)(dyi - 6) : (float)(dxi - 6)) * rain;
        }
    }
    __syncthreads();
    for (int i = threadIdx.x; i < 38 * 128; i += 256) {
        int x = i & 127;
        int lr7 = i - x;
        float a = 0.f;
        #pragma unroll
        for (int u = -3; u <= 3; u++) {
            int xc = min(max(x + u, 0), 127);
            a += GW[u + 3] * s_in[lr7 + xc];
        }
        s_h[i] = a;
    }
    __syncthreads();
    const float* rimg = g_rain + (img & 15) * IMG + 32 * s * 128;
    for (int i = threadIdx.x; i < 32 * 128; i += 256) {
        int j = i >> 7, x = i & 127;
        float a = 0.f;
        #pragma unroll
        for (int u = -3; u <= 3; u++)
            a += GW[u + 3] * s_h[((j + 3 + u) << 7) + x];
        if (mode) a *= rimg[i];
        out[i] = a;
    }
}

// ---------------- K2: patch cost + argmin (prev fully register-resident) --
// block = (batch, dyi, dxhalf): 416 blocks, 512 threads
// smem: s_curr[128][141] | region2 = union{ s_prev[128][132] (init only),
//        s_hsumT[128][156] (transposed; hsum row r at local row r+14,
//        pad rows local 4..13 and 142..151 zeroed) }
__global__ void __launch_bounds__(512) k_cost() {
    extern __shared__ float sm[];
    float* s_curr  = sm;
    float* s_hsumT = sm + SW * CSTR;   // overlaid with s_prev
    float* s_prev  = s_hsumT;          // alias (valid only until p extracted)

    int blk  = blockIdx.x;
    int b    = blk / 26;
    int r26  = blk - b * 26;
    int dyi  = r26 >> 1;
    int half = r26 & 1;
    int dy   = dyi - 6;
    int dx0  = half ? 7 : 0;
    int dx1  = half ? 13 : 7;
    int t    = threadIdx.x;

    const float* pb = g_pblur + b * IMG;
    const float* cb = g_pblur + NPIX + b * IMG;

    for (int i = t; i < IMG; i += 512) {
        int r = i >> 7, c = i & 127;
        s_prev[r * PSTR + c] = pb[i];
    }
    for (int i = t; i < SW * 140; i += 512) {
        int r = i / 140;
        int c = i - r * 140 - 6;                 // -6..133
        int rs = min(max(r + dy, 0), 127);
        int cs = min(max(c, 0), 127);
        s_curr[r * CSTR + (c + 6)] = cb[(rs << 7) + cs];
    }
    __syncthreads();

    const int hr  = t & 127;           // h-pass row
    const int hc0 = (t >> 7) << 5;     // h-pass cols [hc0, hc0+32)
    const int col = t & 127;           // v-pass column
    const int r0  = (t >> 7) << 5;     // v-pass rows [r0, r0+32)

    // ---- extract prev window ONCE into registers (dx-invariant) ----
    float p[56];
    {
        const float4* pv = reinterpret_cast<const float4*>(s_prev + hr * PSTR + hc0 - 12);
        #pragma unroll
        for (int j = 0; j < 14; j++) {
            float4 q = pv[j];
            p[4*j] = q.x; p[4*j+1] = q.y; p[4*j+2] = q.z; p[4*j+3] = q.w;
        }
    }
    __syncthreads();   // all p extracted before hsumT region is overwritten

    // zero hsumT pad rows (local 4..13 = global -10..-1; local 142..151 = 128..137)
    for (int i = t; i < 20 * SW; i += 512) {
        int row = i >> 7;
        int lr = (row < 10) ? (row + 4) : (row + 132);
        s_hsumT[(i & 127) * TSTR + lr] = 0.f;
    }

    unsigned kmin[32];
    #pragma unroll
    for (int k = 0; k < 32; k++) kmin[k] = 0xFFFFFFFFu;

    #pragma unroll 1
    for (int dxi = dx0; dxi < dx1; dxi++) {
        int dx = dxi - 6;
        // ---- h-pass: prev in regs, curr scalar, store transposed ----
        {
            const float* cr = s_curr + hr * CSTR + 6 + dx;   // cr[c] = curr[hr][clamp(c+dx)]
            float* hT = s_hsumT + hr + 14;
            float w = 0.f;
            #pragma unroll
            for (int u = -10; u <= 10; u++) {
                int c = hc0 + u;
                if ((unsigned)c < 128u) { float d = p[u + 12] - cr[c]; w += d * d; }
            }
            #pragma unroll
            for (int k = 0; k < 32; k++) {
                hT[(hc0 + k) * TSTR] = w;
                if (k < 31) {
                    int ca = hc0 + k + 11;
                    if (ca < 128) { float d = p[k + 23] - cr[ca]; w += d * d; }
                    int cs2 = hc0 + k - 10;
                    if (cs2 >= 0) { float d = p[k + 2] - cr[cs2]; w -= d * d; }
                }
            }
        }
        __syncthreads();
        // ---- v-pass: two 16-row chunks, aligned float4 windows, reg slide ----
        {
            unsigned idx = (unsigned)(dyi * 13 + dxi);
            // chunk 0: outputs r0..r0+15 ; window global rows r0-10..r0+25 = local r0+4..r0+39
            {
                float v[36];
                const float4* hv = reinterpret_cast<const float4*>(s_hsumT + col * TSTR + r0 + 4);
                #pragma unroll
                for (int j = 0; j < 9; j++) {
                    float4 q = hv[j];
                    v[4*j] = q.x; v[4*j+1] = q.y; v[4*j+2] = q.z; v[4*j+3] = q.w;
                }
                float w = 0.f;
                #pragma unroll
                for (int j = 0; j < 21; j++) w += v[j];
                #pragma unroll
                for (int k = 0; k < 16; k++) {
                    unsigned key = (__float_as_uint(w) & 0xFFFFFF00u) | idx;
                    kmin[k] = min(kmin[k], key);
                    if (k < 15) { w += v[k + 21]; w -= v[k]; }
                }
            }
            // chunk 1: outputs r0+16..r0+31 ; window global rows r0+6..r0+41 = local r0+20..r0+55
            {
                float v[36];
                const float4* hv = reinterpret_cast<const float4*>(s_hsumT + col * TSTR + r0 + 20);
                #pragma unroll
                for (int j = 0; j < 9; j++) {
                    float4 q = hv[j];
                    v[4*j] = q.x; v[4*j+1] = q.y; v[4*j+2] = q.z; v[4*j+3] = q.w;
                }
                float w = 0.f;
                #pragma unroll
                for (int j = 0; j < 21; j++) w += v[j];
                #pragma unroll
                for (int k = 0; k < 16; k++) {
                    unsigned key = (__float_as_uint(w) & 0xFFFFFF00u) | idx;
                    kmin[16 + k] = min(kmin[16 + k], key);
                    if (k < 15) { w += v[k + 21]; w -= v[k]; }
                }
            }
        }
        __syncthreads();
    }
    unsigned* gb = g_best + b * IMG;
    #pragma unroll
    for (int k = 0; k < 32; k++)
        atomicMin(gb + ((r0 + k) << 7) + col, kmin[k]);
}

// ---------------- K4: upsample flow + warp ref + Huber + mask + reduce ----
__global__ void k_loss(const float* __restrict__ pred, const float* __restrict__ target,
                       const float* __restrict__ ref) {
    int idx4 = blockIdx.x * blockDim.x + threadIdx.x;
    int pix0 = idx4 << 2;
    int b  = pix0 >> 18;
    int p  = pix0 & 262143;
    int oy = p >> 9, ox0 = p & 511;

    float4 pv  = *reinterpret_cast<const float4*>(pred   + pix0);
    float4 tv4 = *reinterpret_cast<const float4*>(target + pix0);
    const float pr4[4] = {pv.x, pv.y, pv.z, pv.w};
    const float tg4[4] = {tv4.x, tv4.y, tv4.z, tv4.w};

    float sy = 0.25f * ((float)oy + 0.5f) - 0.5f; sy = fmaxf(sy, 0.f);
    int iy0 = (int)sy; float wy = sy - (float)iy0; int iy1 = min(iy0 + 1, 127);
    const float* fxp = g_flowb + b * IMG;
    const float* fyp = g_flowb + NPIX + b * IMG;
    const float* rb  = ref + b * (FW * FW);

    float acc = 0.f;
    #pragma unroll
    for (int j = 0; j < 4; j++) {
        int ox = ox0 + j;
        float sx = 0.25f * ((float)ox + 0.5f) - 0.5f; sx = fmaxf(sx, 0.f);
        int ix0 = (int)sx; float wx = sx - (float)ix0; int ix1 = min(ix0 + 1, 127);
        int o00 = (iy0 << 7) + ix0, o01 = (iy0 << 7) + ix1;
        int o10 = (iy1 << 7) + ix0, o11 = (iy1 << 7) + ix1;
        float w00 = (1.f - wy) * (1.f - wx), w01 = (1.f - wy) * wx;
        float w10 = wy * (1.f - wx),        w11 = wy * wx;
        float fx = (fxp[o00]*w00 + fxp[o01]*w01 + fxp[o10]*w10 + fxp[o11]*w11) * 4.0f;
        float fy = (fyp[o00]*w00 + fyp[o01]*w01 + fyp[o10]*w10 + fyp[o11]*w11) * 4.0f;
        float X = fminf(fmaxf((float)ox - fx, 0.f), 511.f);
        float Y = fminf(fmaxf((float)oy - fy, 0.f), 511.f);
        int x0 = (int)X; float ax = X - (float)x0; int x1 = min(x0 + 1, 511);
        int y0 = (int)Y; float ay = Y - (float)y0; int y1 = min(y0 + 1, 511);
        float v00 = rb[y0 * FW + x0], v01 = rb[y0 * FW + x1];
        float v10 = rb[y1 * FW + x0], v11 = rb[y1 * FW + x1];
        float tv = v00 * (1.f - ay) * (1.f - ax) + v01 * (1.f - ay) * ax +
                   v10 * ay * (1.f - ax)         + v11 * ay * ax;
        float teacher = fmaxf(tv, 0.f);
        float d  = pr4[j] - teacher;
        float ad = fabsf(d);
        float l  = (ad < 0.2f) ? (0.5f * d * d) : (0.2f * (ad - 0.1f));
        float m  = (teacher > 0.05f || tg4[j] > 0.05f) ? 1.f : 0.f;
        acc += l * m;
    }
    __shared__ float sred[256];
    sred[threadIdx.x] = acc;
    __syncthreads();
    for (int s = 128; s > 0; s >>= 1) {
        if (threadIdx.x < s) sred[threadIdx.x] += sred[threadIdx.x + s];
        __syncthreads();
    }
    if (threadIdx.x == 0) g_partial[blockIdx.x] = sred[0];
}

__global__ void k_final(float* __restrict__ out) {
    __shared__ float sred[1024];
    int t = threadIdx.x;
    sred[t] = g_partial[t] + g_partial[t + 1024] + g_partial[t + 2048] + g_partial[t + 3072];
    __syncthreads();
    for (int s = 512; s > 0; s >>= 1) {
        if (t < s) sred[t] += sred[t + s];
        __syncthreads();
    }
    if (t == 0) out[0] = sred[0] * (1.0f / 4194304.0f);
}

// ---------------------------------------------------------------------------
extern "C" void kernel_launch(void* const* d_in, const int* in_sizes, int n_in,
                              void* d_out, int out_size) {
    const float* pred   = (const float*)d_in[0];
    const float* target = (const float*)d_in[1];
    const float* ref    = (const float*)d_in[2];
    float* out = (float*)d_out;

    const int costSmem = SW * (CSTR + TSTR) * (int)sizeof(float);   // 152064
    cudaFuncSetAttribute(k_cost, cudaFuncAttributeMaxDynamicSharedMemorySize, costSmem);

    k_prepare<<<NPIX / 256, 256>>>(target, ref);   // launch 0
    k_blur<<<64, 256>>>(0, 0);                     // launch 1
    k_blur<<<64, 256>>>(0, 16);                    // launch 2
    k_cost<<<NB * 13 * 2, 512, costSmem>>>();      // launch 3  <- profiler slot
    k_blur<<<128, 256>>>(1, 0);                    // launch 4
    k_loss<<<4096, 256>>>(pred, target, ref);      // launch 5
    k_final<<<1, 1024>>>(out);                     // launch 6
}